// round 3
// baseline (speedup 1.0000x reference)
#include <cuda_runtime.h>
#include <math.h>

#define HALF_DT 0.005f
#define BATCH   32
#define DM      2048
#define DV      2047
#define DL      512
#define D_PER_CTA 16
#define ZSTR    (DL + 4)   // 516 floats: lane stride mod 32 == 4 -> conflict-free LDS.128

// scratch for v = tanh(z0 @ W^T + b), layout [b][d]
__device__ float g_v[BATCH * DM];

// ---------------------------------------------------------------------------
// Kernel A: v[b,d] = tanh( sum_k z0[b,k] * W[d,k] + bias[d] )
// 128 CTAs x 256 threads. lane = batch, warp = d-group; each thread does 2 d's.
// z0 (66KB) staged in padded smem; W rows are warp-uniform -> L1 broadcast.
// ---------------------------------------------------------------------------
__global__ void __launch_bounds__(256, 1)
gemm_tanh_kernel(const float* __restrict__ z0,
                 const float* __restrict__ W,
                 const float* __restrict__ bias) {
    extern __shared__ float zs[];   // [BATCH][ZSTR]
    const int tid  = threadIdx.x;
    const int lane = tid & 31;
    const int w    = tid >> 5;

    // stage z0 -> smem (coalesced global reads)
    for (int idx = tid; idx < BATCH * DL; idx += 256) {
        int b = idx >> 9;        // / 512
        int k = idx & (DL - 1);
        zs[b * ZSTR + k] = z0[idx];
    }
    __syncthreads();

    const int d0 = blockIdx.x * D_PER_CTA + w;        // always < DV (max 2039)
    const int d1 = d0 + 8;                            // may be 2047 (invalid)
    const bool d1ok = (d1 < DV);
    const int d1c = d1ok ? d1 : 0;                    // compute garbage, don't store

    const float4* __restrict__ zrow = (const float4*)(zs + lane * ZSTR);
    const float4* __restrict__ W0 = (const float4*)(W + (size_t)d0  * DL);
    const float4* __restrict__ W1 = (const float4*)(W + (size_t)d1c * DL);

    float acc0 = 0.f, acc1 = 0.f;
#pragma unroll 8
    for (int k = 0; k < DL / 4; k++) {
        float4 z = zrow[k];
        float4 a = __ldg(&W0[k]);
        float4 c = __ldg(&W1[k]);
        acc0 += z.x * a.x + z.y * a.y + z.z * a.z + z.w * a.w;
        acc1 += z.x * c.x + z.y * c.y + z.z * c.z + z.w * c.w;
    }

    g_v[lane * DM + d0] = tanhf(acc0 + __ldg(&bias[d0]));
    if (d1ok)
        g_v[lane * DM + d1] = tanhf(acc1 + __ldg(&bias[d1]));
}

// ---------------------------------------------------------------------------
// Kernel B: per-batch Cayley solve via Jacobi fixed point.
//   sv[i] = half_dt * v[i]            (sv[-1] = sv[DV] = 0 via padding)
//   rhs   = (I + N) h,  (N x)[i] = sv[i]*x[i+1] - sv[i-1]*x[i-1]
//   x <- rhs + N x, 8 sweeps (contraction factor <= 0.01 per sweep)
// 32 CTAs (one per batch) x 512 threads, 4 elements/thread, all in smem.
// ---------------------------------------------------------------------------
#define NTHREADS 512
#define EPT      (DM / NTHREADS)   // 4
#define N_ITERS  8

__global__ void __launch_bounds__(NTHREADS, 1)
solve_kernel(const float* __restrict__ h,
             float* __restrict__ out) {
    __shared__ float sv_s[DM + 1];   // svp = sv_s+1; svp[-1..DV], zeros at edges
    __shared__ float rs[DM];
    __shared__ float xs_s[DM + 2];   // xp = xs_s+1; xp[-1..DM], zeros at edges

    const int b   = blockIdx.x;
    const int tid = threadIdx.x;
    float* svp = sv_s + 1;
    float* xp  = xs_s + 1;

    if (tid == 0) {
        svp[-1] = 0.f; svp[DV] = 0.f;
        xp[-1]  = 0.f; xp[DM]  = 0.f;
    }
    const float* vrow = g_v + (size_t)b * DM;
    const float* hrow = h   + (size_t)b * DM;
    for (int i = tid; i < DV; i += NTHREADS)
        svp[i] = HALF_DT * vrow[i];
    for (int i = tid; i < DM; i += NTHREADS)
        xp[i] = hrow[i];                      // x0 = h
    __syncthreads();

    // rhs = (I + N) h
#pragma unroll
    for (int j = 0; j < EPT; j++) {
        int i = tid + j * NTHREADS;
        rs[i] = xp[i] + svp[i] * xp[i + 1] - svp[i - 1] * xp[i - 1];
    }
    __syncthreads();

    for (int it = 0; it < N_ITERS; it++) {
        float xn[EPT];
#pragma unroll
        for (int j = 0; j < EPT; j++) {
            int i = tid + j * NTHREADS;
            xn[j] = rs[i] + svp[i] * xp[i + 1] - svp[i - 1] * xp[i - 1];
        }
        __syncthreads();
#pragma unroll
        for (int j = 0; j < EPT; j++)
            xp[tid + j * NTHREADS] = xn[j];
        __syncthreads();
    }

    float* orow = out + (size_t)b * DM;
#pragma unroll
    for (int j = 0; j < EPT; j++) {
        int i = tid + j * NTHREADS;
        orow[i] = xp[i];
    }
}

// ---------------------------------------------------------------------------
extern "C" void kernel_launch(void* const* d_in, const int* in_sizes, int n_in,
                              void* d_out, int out_size) {
    const float* z0   = (const float*)d_in[0];   // (32, 512)
    const float* h    = (const float*)d_in[1];   // (32, 2048)
    const float* W    = (const float*)d_in[2];   // (2047, 512)
    const float* bias = (const float*)d_in[3];   // (2047,)
    float* out = (float*)d_out;                  // (32, 2048)

    const int smemA = BATCH * ZSTR * (int)sizeof(float);   // 66048 B
    static bool attr_done = false;
    if (!attr_done) {
        cudaFuncSetAttribute(gemm_tanh_kernel,
                             cudaFuncAttributeMaxDynamicSharedMemorySize, smemA);
        attr_done = true;
    }

    gemm_tanh_kernel<<<(DV + D_PER_CTA - 1) / D_PER_CTA, 256, smemA>>>(z0, W, bias);
    solve_kernel<<<BATCH, NTHREADS>>>(h, out);
}

// round 5
// speedup vs baseline: 1.2429x; 1.2429x over previous
#include <cuda_runtime.h>
#include <math.h>

#define HALF_DT 0.005f
#define BATCH   32
#define DM      2048
#define DV      2047
#define DL      512
#define D_PER_CTA 16
#define ZSTR    (DL + 4)   // 516 floats: conflict-free LDS.128 across 8-lane phases

// scratch: g_v[b][d] = HALF_DT * tanh(z0[b]·W[d] + bias[d])   (d < DV; d=DV unset)
__device__ float g_v[BATCH * DM];

// ---------------------------------------------------------------------------
// Kernel A: 128 CTAs x 512 threads (16 warps). warp = one d-row, lane = batch.
// z0 (66KB) staged in padded smem; W row is warp-uniform -> L1 broadcast.
// ---------------------------------------------------------------------------
__global__ void __launch_bounds__(512, 1)
gemm_tanh_kernel(const float* __restrict__ z0,
                 const float* __restrict__ W,
                 const float* __restrict__ bias) {
    extern __shared__ float zs[];   // [BATCH][ZSTR]
    const int tid  = threadIdx.x;
    const int lane = tid & 31;
    const int w    = tid >> 5;

    for (int idx = tid; idx < BATCH * DL; idx += 512) {
        int b = idx >> 9;
        int k = idx & (DL - 1);
        zs[b * ZSTR + k] = z0[idx];
    }
    __syncthreads();

    const int d = blockIdx.x * D_PER_CTA + w;     // 0..2047; 2047 invalid
    const bool dok = (d < DV);
    const int dc = dok ? d : 0;

    const float4* __restrict__ zrow = (const float4*)(zs + lane * ZSTR);
    const float4* __restrict__ Wr   = (const float4*)(W + (size_t)dc * DL);

    float acc = 0.f;
#pragma unroll 16
    for (int k = 0; k < DL / 4; k++) {
        float4 z = zrow[k];
        float4 a = __ldg(&Wr[k]);
        acc += z.x * a.x + z.y * a.y + z.z * a.z + z.w * a.w;
    }

    if (dok)
        g_v[lane * DM + d] = HALF_DT * tanhf(acc + __ldg(&bias[d]));
}

// ---------------------------------------------------------------------------
// Kernel B: per-batch Cayley solve via truncated Neumann series (NO iteration):
//   x = (I-N)^{-1}(I+N) h = h + 2Nh + 2N^2h + 2N^3h + O(||N||^4),  ||N|| <= 0.01
//   (N x)[i] = sv[i]*x[i+1] - sv[i-1]*x[i-1],  sv zero-padded at both ends.
// Truncation error ~2e-8 relative. 3 stencil passes, 3 barriers.
// 32 CTAs (one per batch) x 512 threads, 4 elements/thread, all in smem.
// ---------------------------------------------------------------------------
#define NTHREADS 512
#define EPT      (DM / NTHREADS)   // 4

__global__ void __launch_bounds__(NTHREADS, 1)
solve_kernel(const float* __restrict__ h,
             float* __restrict__ out) {
    __shared__ float hs_s[DM + 2];   // hp = +1; hp[-1..DM], zero edges
    __shared__ float sv_s[DM + 2];   // svp = +1; svp[-1..DM], zero edges
    __shared__ float y1_s[DM + 2];
    __shared__ float y2_s[DM + 2];

    const int b   = blockIdx.x;
    const int tid = threadIdx.x;
    float* hp  = hs_s + 1;
    float* svp = sv_s + 1;
    float* y1  = y1_s + 1;
    float* y2  = y2_s + 1;

    if (tid == 0) {
        hp[-1]  = 0.f; hp[DM]  = 0.f;
        svp[-1] = 0.f; svp[DV] = 0.f;
        y1[-1]  = 0.f; y1[DM]  = 0.f;
        y2[-1]  = 0.f; y2[DM]  = 0.f;
    }
    // vectorized loads: both rows are 16B-aligned (DM*4 bytes per row)
    const float4* vrow4 = (const float4*)(g_v + (size_t)b * DM);
    const float4* hrow4 = (const float4*)(h   + (size_t)b * DM);
#pragma unroll
    for (int j = 0; j < DM / (4 * NTHREADS); j++) {   // 1 iter
        int i4 = tid + j * NTHREADS;                  // float4 index, 0..511
        float4 hv = hrow4[i4];
        float4 vv = vrow4[i4];
        int i = i4 * 4;
        hp[i]   = hv.x; hp[i+1] = hv.y; hp[i+2] = hv.z; hp[i+3] = hv.w;
        svp[i]   = vv.x; svp[i+1] = vv.y; svp[i+2] = vv.z;
        if (i + 3 < DV) svp[i+3] = vv.w;              // skip unset g_v[...][2047]
    }
    __syncthreads();

    float acc[EPT];
    // pass 1: y1 = N h ; acc = h + 2*y1
#pragma unroll
    for (int j = 0; j < EPT; j++) {
        int i = tid + j * NTHREADS;
        float t = svp[i] * hp[i + 1] - svp[i - 1] * hp[i - 1];
        y1[i] = t;
        acc[j] = hp[i] + 2.f * t;
    }
    __syncthreads();

    // pass 2: y2 = N y1 ; acc += 2*y2
#pragma unroll
    for (int j = 0; j < EPT; j++) {
        int i = tid + j * NTHREADS;
        float t = svp[i] * y1[i + 1] - svp[i - 1] * y1[i - 1];
        y2[i] = t;
        acc[j] += 2.f * t;
    }
    __syncthreads();

    // pass 3: acc += 2 * N y2 ; store
    float* orow = out + (size_t)b * DM;
#pragma unroll
    for (int j = 0; j < EPT; j++) {
        int i = tid + j * NTHREADS;
        float t = svp[i] * y2[i + 1] - svp[i - 1] * y2[i - 1];
        orow[i] = acc[j] + 2.f * t;
    }
}

// ---------------------------------------------------------------------------
extern "C" void kernel_launch(void* const* d_in, const int* in_sizes, int n_in,
                              void* d_out, int out_size) {
    const float* z0   = (const float*)d_in[0];   // (32, 512)
    const float* h    = (const float*)d_in[1];   // (32, 2048)
    const float* W    = (const float*)d_in[2];   // (2047, 512)
    const float* bias = (const float*)d_in[3];   // (2047,)
    float* out = (float*)d_out;                  // (32, 2048)

    const int smemA = BATCH * ZSTR * (int)sizeof(float);   // 66048 B
    static bool attr_done = false;
    if (!attr_done) {
        cudaFuncSetAttribute(gemm_tanh_kernel,
                             cudaFuncAttributeMaxDynamicSharedMemorySize, smemA);
        attr_done = true;
    }

    gemm_tanh_kernel<<<(DV + D_PER_CTA - 1) / D_PER_CTA, 512, smemA>>>(z0, W, bias);
    solve_kernel<<<BATCH, NTHREADS>>>(h, out);
}